// round 7
// baseline (speedup 1.0000x reference)
#include <cuda_runtime.h>

#define MAXN 100000
#define DDIM 64

// Scratch (device globals: allocation-free per harness rules)
__device__ float g_agg[MAXN * DDIM];   // per-layer aggregation accumulator
__device__ float g_h[MAXN * DDIM];     // hidden activations after layer 1
__device__ float g_cnt[MAXN];          // in-degree (float), computed once
__device__ int   g_idx64;              // 1 if edge_index is int64, 0 if int32

// Packed f32x2 helpers (Blackwell, PTX ISA 8.6)
#define PK(d, lo, hi) \
    asm("mov.b64 %0, {%1, %2};" : "=l"(d) : "r"(__float_as_uint(lo)), "r"(__float_as_uint(hi)))
#define FMA2(acc, a, b) \
    asm("fma.rn.f32x2 %0, %1, %2, %0;" : "+l"(acc) : "l"(a), "l"(b))
#define UPK(lo, hi, v) \
    asm("mov.b64 {%0, %1}, %2;" : "=r"(lo), "=r"(hi) : "l"(v))

// ---------------------------------------------------------------------------
// Detect edge_index dtype (int32 read as int64 -> values far outside [0,N)).
// ---------------------------------------------------------------------------
__global__ void detect_kernel(const long long* __restrict__ ei, int nprobe, int N) {
    if (threadIdx.x == 0 && blockIdx.x == 0) {
        int is64 = 1;
        for (int i = 0; i < nprobe; i++) {
            long long v = ei[i];
            if (v < 0 || v >= (long long)N) { is64 = 0; break; }
        }
        g_idx64 = is64;
    }
}

// ---------------------------------------------------------------------------
// Zero the aggregation buffer (and optionally the count buffer)
// ---------------------------------------------------------------------------
__global__ void zero_kernel(int nf4, int ncnt) {
    int stride = gridDim.x * blockDim.x;
    int tid = blockIdx.x * blockDim.x + threadIdx.x;
    float4 z = make_float4(0.f, 0.f, 0.f, 0.f);
    float4* a = reinterpret_cast<float4*>(g_agg);
    for (int k = tid; k < nf4; k += stride) a[k] = z;
    for (int k = tid; k < ncnt; k += stride) g_cnt[k] = 0.f;
}

// ---------------------------------------------------------------------------
// Edge scatter (UNCHANGED from passing kernel): 16 threads/edge, vector RED.
// ---------------------------------------------------------------------------
template <bool COUNT>
__global__ __launch_bounds__(256)
void scatter_kernel(const float4* __restrict__ x4,
                    const void* __restrict__ ei_raw,
                    const float* __restrict__ ew,
                    int E) {
    long long t = (long long)blockIdx.x * 256 + threadIdx.x;
    int e = (int)(t >> 4);
    if (e >= E) return;
    int lane = (int)t & 15;

    int src, dst;
    if (g_idx64) {
        const long long* ei = (const long long*)ei_raw;
        src = (int)ei[e];
        dst = (int)ei[(long long)E + e];
    } else {
        const int* ei = (const int*)ei_raw;
        src = ei[e];
        dst = ei[E + e];
    }
    float w = ew[e];

    if (COUNT && lane == 0) {
        atomicAdd(&g_cnt[dst], 1.0f);
    }

    float4 v = x4[(long long)src * 16 + lane];
    v.x *= w; v.y *= w; v.z *= w; v.w *= w;

    float4* p = reinterpret_cast<float4*>(&g_agg[(long long)dst * 64 + lane * 4]);
#if __CUDA_ARCH__ >= 900
    atomicAdd(p, v);               // vector red.global.add.v4.f32
#else
    atomicAdd(&p->x, v.x);
    atomicAdd(&p->y, v.y);
    atomicAdd(&p->z, v.z);
    atomicAdd(&p->w, v.w);
#endif
}

// ---------------------------------------------------------------------------
// Combine v3: packed-f32x2 dual GEMM.
// Block: 256 nodes x 64 outputs, 256 threads (tn=tid>>2: 64 groups of 4 nodes;
// ti=tid&3: 4 groups of 16 outputs = 8 f32x2 pairs).
// acc[u][p]: node u (0..3) x output-pair p (0..7), 64-bit packed.
//   a: float4 over j from sT (stride-68 padded rows)
//   b: 4x float4 per j from transposed sW, packed to f32x2 pairs
// FFMA2 rate = 2 FMA / rt2 -> 2x scalar FFMA roofline.
// ---------------------------------------------------------------------------
#define ST_STRIDE 68   // 64 + 4 pad: float4-aligned, breaks bank-conflict stride

__device__ __forceinline__ void gemm_pass(const float* __restrict__ sT,
                                          const float* __restrict__ sW,
                                          int tn, int ti,
                                          unsigned long long acc[4][8]) {
    #pragma unroll 2
    for (int j4 = 0; j4 < 64; j4 += 4) {
        float4 a4[4];
        #pragma unroll
        for (int u = 0; u < 4; u++)
            a4[u] = *reinterpret_cast<const float4*>(&sT[(4 * tn + u) * ST_STRIDE + j4]);
        #pragma unroll
        for (int jj = 0; jj < 4; jj++) {
            const float* wrow = &sW[(j4 + jj) * 64 + 16 * ti];
            float4 b0 = *reinterpret_cast<const float4*>(wrow);
            float4 b1 = *reinterpret_cast<const float4*>(wrow + 4);
            float4 b2 = *reinterpret_cast<const float4*>(wrow + 8);
            float4 b3 = *reinterpret_cast<const float4*>(wrow + 12);
            unsigned long long bb[8];
            PK(bb[0], b0.x, b0.y); PK(bb[1], b0.z, b0.w);
            PK(bb[2], b1.x, b1.y); PK(bb[3], b1.z, b1.w);
            PK(bb[4], b2.x, b2.y); PK(bb[5], b2.z, b2.w);
            PK(bb[6], b3.x, b3.y); PK(bb[7], b3.z, b3.w);
            #pragma unroll
            for (int u = 0; u < 4; u++) {
                float aj = (jj == 0) ? a4[u].x : (jj == 1) ? a4[u].y
                         : (jj == 2) ? a4[u].z : a4[u].w;
                unsigned long long aa;
                PK(aa, aj, aj);
                #pragma unroll
                for (int p = 0; p < 8; p++) FMA2(acc[u][p], aa, bb[p]);
            }
        }
    }
}

template <bool RELU>
__global__ __launch_bounds__(256, 2)
void combine_kernel(const float* __restrict__ in,
                    const float* __restrict__ Ws, const float* __restrict__ bs,
                    const float* __restrict__ Wn, const float* __restrict__ bn,
                    const float* __restrict__ wp,
                    float* __restrict__ out, int N) {
    extern __shared__ float smem[];
    float* sW = smem;                 // 64*64
    float* sT = smem + 64 * 64;       // 256*ST_STRIDE

    int tid = threadIdx.x;
    int n0 = blockIdx.x * 256;
    int tn = tid >> 2, ti = tid & 3;
    float wpv = wp[0];

    // --- load Ws transposed ---
    #pragma unroll
    for (int r = 0; r < 16; r++) {
        int idx = r * 256 + tid;
        int j = idx >> 6, i = idx & 63;
        sW[idx] = Ws[i * 64 + j];
    }
    // --- load input tile (256 rows x 16 float4) ---
    #pragma unroll
    for (int r = 0; r < 16; r++) {
        int idx = r * 256 + tid;
        int n = idx >> 4, q = idx & 15;
        int gn = n0 + n;
        float4 v = make_float4(0.f, 0.f, 0.f, 0.f);
        if (gn < N) v = reinterpret_cast<const float4*>(in)[(long long)gn * 16 + q];
        *reinterpret_cast<float4*>(&sT[n * ST_STRIDE + 4 * q]) = v;
    }
    __syncthreads();

    unsigned long long acc[4][8];
    #pragma unroll
    for (int u = 0; u < 4; u++)
        #pragma unroll
        for (int p = 0; p < 8; p++) acc[u][p] = 0ull;

    // --- pass 1: in @ Ws^T ---
    gemm_pass(sT, sW, tn, ti, acc);
    __syncthreads();

    // --- reload: Wn transposed + scaled agg tile ---
    #pragma unroll
    for (int r = 0; r < 16; r++) {
        int idx = r * 256 + tid;
        int j = idx >> 6, i = idx & 63;
        sW[idx] = Wn[i * 64 + j];
    }
    #pragma unroll
    for (int r = 0; r < 16; r++) {
        int idx = r * 256 + tid;
        int n = idx >> 4, q = idx & 15;
        int gn = n0 + n;
        float4 v = make_float4(0.f, 0.f, 0.f, 0.f);
        if (gn < N) {
            float inv = wpv / fmaxf(g_cnt[gn], 1.0f);
            v = reinterpret_cast<const float4*>(g_agg)[(long long)gn * 16 + q];
            v.x *= inv; v.y *= inv; v.z *= inv; v.w *= inv;
        }
        *reinterpret_cast<float4*>(&sT[n * ST_STRIDE + 4 * q]) = v;
    }
    __syncthreads();

    // --- pass 2: agg @ Wn^T ---
    gemm_pass(sT, sW, tn, ti, acc);

    // --- epilogue: bias (+ReLU), vectorized store ---
    float4 bias[4];
    #pragma unroll
    for (int k = 0; k < 4; k++) {
        float4 bsv = reinterpret_cast<const float4*>(bs)[4 * ti + k];
        float4 bnv = reinterpret_cast<const float4*>(bn)[4 * ti + k];
        bias[k] = make_float4(bsv.x + bnv.x, bsv.y + bnv.y,
                              bsv.z + bnv.z, bsv.w + bnv.w);
    }
    #pragma unroll
    for (int u = 0; u < 4; u++) {
        int gn = n0 + 4 * tn + u;
        if (gn < N) {
            #pragma unroll
            for (int k = 0; k < 4; k++) {
                unsigned int l0, h0, l1, h1;
                UPK(l0, h0, acc[u][2 * k]);
                UPK(l1, h1, acc[u][2 * k + 1]);
                float4 val;
                val.x = __uint_as_float(l0) + bias[k].x;
                val.y = __uint_as_float(h0) + bias[k].y;
                val.z = __uint_as_float(l1) + bias[k].z;
                val.w = __uint_as_float(h1) + bias[k].w;
                if (RELU) {
                    val.x = fmaxf(val.x, 0.f); val.y = fmaxf(val.y, 0.f);
                    val.z = fmaxf(val.z, 0.f); val.w = fmaxf(val.w, 0.f);
                }
                reinterpret_cast<float4*>(out)[(long long)gn * 16 + 4 * ti + k] = val;
            }
        }
    }
}

// ---------------------------------------------------------------------------
// Launch: detect -> zero -> scatter(x)+count -> combine1(relu->h)
//         -> zero -> scatter(h) -> combine2(->out)
// ---------------------------------------------------------------------------
extern "C" void kernel_launch(void* const* d_in, const int* in_sizes, int n_in,
                              void* d_out, int out_size) {
    const float* x       = (const float*)d_in[0];
    const void*  ei      = d_in[1];                 // int32 or int64 (detected)
    const float* ew      = (const float*)d_in[2];
    const float* Ws1 = (const float*)d_in[3];
    const float* bs1 = (const float*)d_in[4];
    const float* Wn1 = (const float*)d_in[5];
    const float* bn1 = (const float*)d_in[6];
    const float* wp1 = (const float*)d_in[7];
    const float* Ws2 = (const float*)d_in[8];
    const float* bs2 = (const float*)d_in[9];
    const float* Wn2 = (const float*)d_in[10];
    const float* bn2 = (const float*)d_in[11];
    const float* wp2 = (const float*)d_in[12];

    int N = in_sizes[0] / DDIM;
    int E = in_sizes[2];
    float* out = (float*)d_out;

    // Resolve DEVICE address of g_h (host shadow symbol is not a device ptr).
    void* h_ptr_v = nullptr;
    cudaGetSymbolAddress(&h_ptr_v, g_h);
    float* h_ptr = (float*)h_ptr_v;

    int smem_bytes = (64 * 64 + 256 * ST_STRIDE) * (int)sizeof(float);  // 84 KB
    cudaFuncSetAttribute(combine_kernel<true>,
                         cudaFuncAttributeMaxDynamicSharedMemorySize, smem_bytes);
    cudaFuncSetAttribute(combine_kernel<false>,
                         cudaFuncAttributeMaxDynamicSharedMemorySize, smem_bytes);

    int nf4 = N * (DDIM / 4);
    int zero_blocks = (nf4 + 255) / 256;
    long long sthreads = (long long)E * 16;
    int sblocks = (int)((sthreads + 255) / 256);
    int cblocks = (N + 255) / 256;
    int nprobe = (E > 32) ? 32 : E;

    detect_kernel<<<1, 32>>>((const long long*)ei, nprobe, N);

    // Layer 1
    zero_kernel<<<zero_blocks, 256>>>(nf4, N);
    scatter_kernel<true><<<sblocks, 256>>>((const float4*)x, ei, ew, E);
    combine_kernel<true><<<cblocks, 256, smem_bytes>>>(x, Ws1, bs1, Wn1, bn1, wp1, h_ptr, N);

    // Layer 2
    zero_kernel<<<zero_blocks, 256>>>(nf4, 0);
    scatter_kernel<false><<<sblocks, 256>>>((const float4*)h_ptr, ei, ew, E);
    combine_kernel<false><<<cblocks, 256, smem_bytes>>>(h_ptr, Ws2, bs2, Wn2, bn2, wp2, out, N);
}

// round 8
// speedup vs baseline: 1.3909x; 1.3909x over previous
#include <cuda_runtime.h>

#define MAXN 100000
#define MAXE 2000000
#define DDIM 64
#define NB_MAX 512          // max histogram blocks for the scan (N/256)

// Scratch (device globals: allocation-free per harness rules)
__device__ float g_agg[MAXN * DDIM];   // per-layer aggregation accumulator
__device__ float g_h[MAXN * DDIM];     // hidden activations after layer 1
__device__ float g_cnt[MAXN];          // in-degree (float)
__device__ int   g_deg[MAXN];          // in-degree (int, histogram)
__device__ int   g_off[MAXN];          // CSR row offsets
__device__ int   g_cur[MAXN];          // reorder cursors
__device__ int   g_bsum[NB_MAX];       // per-block sums for the scan
__device__ int2  g_edge[MAXE];         // CSR payload: {src, float_bits(w)}
__device__ int   g_idx64;              // 1 if edge_index is int64, 0 if int32

// ---------------------------------------------------------------------------
// Detect edge_index dtype (int32 read as int64 -> values far outside [0,N)).
// ---------------------------------------------------------------------------
__global__ void detect_kernel(const long long* __restrict__ ei, int nprobe, int N) {
    if (threadIdx.x == 0 && blockIdx.x == 0) {
        int is64 = 1;
        for (int i = 0; i < nprobe; i++) {
            long long v = ei[i];
            if (v < 0 || v >= (long long)N) { is64 = 0; break; }
        }
        g_idx64 = is64;
    }
}

__device__ __forceinline__ int load_dst(const void* ei_raw, int e, int E) {
    if (g_idx64) return (int)((const long long*)ei_raw)[(long long)E + e];
    return ((const int*)ei_raw)[E + e];
}
__device__ __forceinline__ int load_src(const void* ei_raw, int e) {
    if (g_idx64) return (int)((const long long*)ei_raw)[e];
    return ((const int*)ei_raw)[e];
}

// ---------------------------------------------------------------------------
// CSR construction: zero-deg -> histogram -> block sums -> scan -> offsets
// -> reorder
// ---------------------------------------------------------------------------
__global__ void zerodeg_kernel(int N) {
    int i = blockIdx.x * blockDim.x + threadIdx.x;
    if (i < N) g_deg[i] = 0;
}

__global__ void hist_kernel(const void* __restrict__ ei_raw, int E) {
    int e = blockIdx.x * blockDim.x + threadIdx.x;
    if (e >= E) return;
    atomicAdd(&g_deg[load_dst(ei_raw, e, E)], 1);
}

__global__ void bsum_kernel(int N) {
    __shared__ int s[256];
    int i = blockIdx.x * 256 + threadIdx.x;
    s[threadIdx.x] = (i < N) ? g_deg[i] : 0;
    __syncthreads();
    for (int d = 128; d > 0; d >>= 1) {
        if (threadIdx.x < d) s[threadIdx.x] += s[threadIdx.x + d];
        __syncthreads();
    }
    if (threadIdx.x == 0) g_bsum[blockIdx.x] = s[0];
}

__global__ void bscan_kernel(int nb) {   // single block, exclusive scan in-place
    __shared__ int s[NB_MAX];
    int t = threadIdx.x;
    int v = (t < nb) ? g_bsum[t] : 0;
    s[t] = v;
    __syncthreads();
    for (int d = 1; d < NB_MAX; d <<= 1) {
        int add = (t >= d) ? s[t - d] : 0;
        __syncthreads();
        s[t] += add;
        __syncthreads();
    }
    if (t < nb) g_bsum[t] = s[t] - v;    // exclusive
}

__global__ void off_kernel(int N) {
    __shared__ int s[256];
    int t = threadIdx.x;
    int i = blockIdx.x * 256 + t;
    int d = (i < N) ? g_deg[i] : 0;
    s[t] = d;
    __syncthreads();
    for (int k = 1; k < 256; k <<= 1) {
        int add = (t >= k) ? s[t - k] : 0;
        __syncthreads();
        s[t] += add;
        __syncthreads();
    }
    if (i < N) {
        g_off[i] = g_bsum[blockIdx.x] + s[t] - d;   // exclusive prefix
        g_cnt[i] = (float)d;
        g_cur[i] = 0;
    }
}

__global__ void reorder_kernel(const void* __restrict__ ei_raw,
                               const float* __restrict__ ew, int E) {
    int e = blockIdx.x * blockDim.x + threadIdx.x;
    if (e >= E) return;
    int dst = load_dst(ei_raw, e, E);
    int src = load_src(ei_raw, e);
    int pos = g_off[dst] + atomicAdd(&g_cur[dst], 1);
    g_edge[pos] = make_int2(src, __float_as_int(ew[e]));
}

// ---------------------------------------------------------------------------
// CSR aggregation: 16 threads per destination node; register accumulation,
// single plain store (no atomics). g_agg fully overwritten -> no zeroing.
// ---------------------------------------------------------------------------
__global__ __launch_bounds__(256)
void agg_kernel(const float4* __restrict__ x4, int N) {
    long long t = (long long)blockIdx.x * 256 + threadIdx.x;
    int d = (int)(t >> 4);
    if (d >= N) return;
    int lane = (int)t & 15;

    int off = g_off[d];
    int deg = g_deg[d];
    float4 acc = make_float4(0.f, 0.f, 0.f, 0.f);
    for (int k = 0; k < deg; k++) {
        int2 er = __ldg(&g_edge[off + k]);          // broadcast across 16 lanes
        float w = __int_as_float(er.y);
        float4 v = __ldg(&x4[(long long)er.x * 16 + lane]);
        acc.x += w * v.x; acc.y += w * v.y;
        acc.z += w * v.z; acc.w += w * v.w;
    }
    reinterpret_cast<float4*>(g_agg)[(long long)d * 16 + lane] = acc;
}

// ---------------------------------------------------------------------------
// Combine (PROVEN R6 version, 97.7us — at scalar-FFMA roofline):
//   out[n] = in[n] @ Ws^T + bs + (agg[n] * wp / max(cnt[n],1)) @ Wn^T + bn
// ---------------------------------------------------------------------------
template <bool RELU>
__global__ __launch_bounds__(256, 4)
void combine_kernel(const float* __restrict__ in,
                    const float* __restrict__ Ws, const float* __restrict__ bs,
                    const float* __restrict__ Wn, const float* __restrict__ bn,
                    const float* __restrict__ wp,
                    float* __restrict__ out, int N) {
    __shared__ float sW[64 * 64];   // transposed: sW[j*64+i] = W[i][j]
    __shared__ float sT[64 * 64];   // natural:    sT[n*64+j]

    int tid = threadIdx.x;
    int n0 = blockIdx.x * 64;
    float wpv = wp[0];
    int tn = tid >> 4, ti = tid & 15;

    #pragma unroll
    for (int r = 0; r < 16; r++) {
        int idx = r * 256 + tid;
        int j = idx >> 6, i = idx & 63;
        sW[idx] = Ws[i * 64 + j];
    }
    #pragma unroll
    for (int r = 0; r < 4; r++) {
        int idx = r * 256 + tid;
        int n = idx >> 4, q = idx & 15;
        int gn = n0 + n;
        float4 v = make_float4(0.f, 0.f, 0.f, 0.f);
        if (gn < N) v = reinterpret_cast<const float4*>(in)[(long long)gn * 16 + q];
        reinterpret_cast<float4*>(sT)[idx] = v;
    }
    __syncthreads();

    float acc[4][4];
    #pragma unroll
    for (int u = 0; u < 4; u++)
        #pragma unroll
        for (int v = 0; v < 4; v++) acc[u][v] = 0.f;

    #pragma unroll
    for (int j4 = 0; j4 < 64; j4 += 4) {
        float4 a[4], b[4];
        #pragma unroll
        for (int u = 0; u < 4; u++)
            a[u] = *reinterpret_cast<const float4*>(&sT[(4 * tn + u) * 64 + j4]);
        #pragma unroll
        for (int jj = 0; jj < 4; jj++)
            b[jj] = *reinterpret_cast<const float4*>(&sW[(j4 + jj) * 64 + 4 * ti]);
        #pragma unroll
        for (int u = 0; u < 4; u++) {
            acc[u][0] += a[u].x * b[0].x + a[u].y * b[1].x + a[u].z * b[2].x + a[u].w * b[3].x;
            acc[u][1] += a[u].x * b[0].y + a[u].y * b[1].y + a[u].z * b[2].y + a[u].w * b[3].y;
            acc[u][2] += a[u].x * b[0].z + a[u].y * b[1].z + a[u].z * b[2].z + a[u].w * b[3].z;
            acc[u][3] += a[u].x * b[0].w + a[u].y * b[1].w + a[u].z * b[2].w + a[u].w * b[3].w;
        }
    }
    __syncthreads();

    #pragma unroll
    for (int r = 0; r < 16; r++) {
        int idx = r * 256 + tid;
        int j = idx >> 6, i = idx & 63;
        sW[idx] = Wn[i * 64 + j];
    }
    #pragma unroll
    for (int r = 0; r < 4; r++) {
        int idx = r * 256 + tid;
        int n = idx >> 4, q = idx & 15;
        int gn = n0 + n;
        float4 v = make_float4(0.f, 0.f, 0.f, 0.f);
        if (gn < N) {
            float inv = wpv / fmaxf(g_cnt[gn], 1.0f);
            v = reinterpret_cast<const float4*>(g_agg)[(long long)gn * 16 + q];
            v.x *= inv; v.y *= inv; v.z *= inv; v.w *= inv;
        }
        reinterpret_cast<float4*>(sT)[idx] = v;
    }
    __syncthreads();

    #pragma unroll
    for (int j4 = 0; j4 < 64; j4 += 4) {
        float4 a[4], b[4];
        #pragma unroll
        for (int u = 0; u < 4; u++)
            a[u] = *reinterpret_cast<const float4*>(&sT[(4 * tn + u) * 64 + j4]);
        #pragma unroll
        for (int jj = 0; jj < 4; jj++)
            b[jj] = *reinterpret_cast<const float4*>(&sW[(j4 + jj) * 64 + 4 * ti]);
        #pragma unroll
        for (int u = 0; u < 4; u++) {
            acc[u][0] += a[u].x * b[0].x + a[u].y * b[1].x + a[u].z * b[2].x + a[u].w * b[3].x;
            acc[u][1] += a[u].x * b[0].y + a[u].y * b[1].y + a[u].z * b[2].y + a[u].w * b[3].y;
            acc[u][2] += a[u].x * b[0].z + a[u].y * b[1].z + a[u].z * b[2].z + a[u].w * b[3].z;
            acc[u][3] += a[u].x * b[0].w + a[u].y * b[1].w + a[u].z * b[2].w + a[u].w * b[3].w;
        }
    }

    float4 bsv = reinterpret_cast<const float4*>(bs)[ti];
    float4 bnv = reinterpret_cast<const float4*>(bn)[ti];
    float4 bias = make_float4(bsv.x + bnv.x, bsv.y + bnv.y,
                              bsv.z + bnv.z, bsv.w + bnv.w);
    #pragma unroll
    for (int u = 0; u < 4; u++) {
        int gn = n0 + 4 * tn + u;
        if (gn < N) {
            float4 val;
            val.x = acc[u][0] + bias.x;
            val.y = acc[u][1] + bias.y;
            val.z = acc[u][2] + bias.z;
            val.w = acc[u][3] + bias.w;
            if (RELU) {
                val.x = fmaxf(val.x, 0.f); val.y = fmaxf(val.y, 0.f);
                val.z = fmaxf(val.z, 0.f); val.w = fmaxf(val.w, 0.f);
            }
            reinterpret_cast<float4*>(out)[(long long)gn * 16 + ti] = val;
        }
    }
}

// ---------------------------------------------------------------------------
// Launch: detect -> CSR build (once) -> [agg -> combine] x 2
// ---------------------------------------------------------------------------
extern "C" void kernel_launch(void* const* d_in, const int* in_sizes, int n_in,
                              void* d_out, int out_size) {
    const float* x       = (const float*)d_in[0];
    const void*  ei      = d_in[1];                 // int32 or int64 (detected)
    const float* ew      = (const float*)d_in[2];
    const float* Ws1 = (const float*)d_in[3];
    const float* bs1 = (const float*)d_in[4];
    const float* Wn1 = (const float*)d_in[5];
    const float* bn1 = (const float*)d_in[6];
    const float* wp1 = (const float*)d_in[7];
    const float* Ws2 = (const float*)d_in[8];
    const float* bs2 = (const float*)d_in[9];
    const float* Wn2 = (const float*)d_in[10];
    const float* bn2 = (const float*)d_in[11];
    const float* wp2 = (const float*)d_in[12];

    int N = in_sizes[0] / DDIM;
    int E = in_sizes[2];
    float* out = (float*)d_out;

    // Resolve DEVICE address of g_h (host shadow symbol is not a device ptr).
    void* h_ptr_v = nullptr;
    cudaGetSymbolAddress(&h_ptr_v, g_h);
    float* h_ptr = (float*)h_ptr_v;

    int nblk   = (N + 255) / 256;        // node-grain blocks (also scan blocks)
    int eblk   = (E + 255) / 256;        // edge-grain blocks
    int ablk   = (N * 16 + 255) / 256;   // agg blocks (16 threads/node)
    int cblk   = (N + 63) / 64;          // combine blocks
    int nprobe = (E > 32) ? 32 : E;

    detect_kernel<<<1, 32>>>((const long long*)ei, nprobe, N);

    // --- CSR build (amortized over both layers) ---
    zerodeg_kernel<<<nblk, 256>>>(N);
    hist_kernel<<<eblk, 256>>>(ei, E);
    bsum_kernel<<<nblk, 256>>>(N);
    bscan_kernel<<<1, NB_MAX>>>(nblk);
    off_kernel<<<nblk, 256>>>(N);
    reorder_kernel<<<eblk, 256>>>(ei, ew, E);

    // --- Layer 1 ---
    agg_kernel<<<ablk, 256>>>((const float4*)x, N);
    combine_kernel<true><<<cblk, 256>>>(x, Ws1, bs1, Wn1, bn1, wp1, h_ptr, N);

    // --- Layer 2 ---
    agg_kernel<<<ablk, 256>>>((const float4*)h_ptr, N);
    combine_kernel<false><<<cblk, 256>>>(h_ptr, Ws2, bs2, Wn2, bn2, wp2, out, N);
}